// round 1
// baseline (speedup 1.0000x reference)
#include <cuda_runtime.h>

#define BATCH 16384
#define LSEQ  256
#define CH    32
#define EPSBN 1e-5
#define LOG2PI 1.8378770664093453f

// ---------------- scratch (device-global; no runtime alloc allowed) -------
__device__ float  g_buf1[(size_t)BATCH*CH*LSEQ];   // conv1 output (pre-BN), 512MB
__device__ float  g_buf2[(size_t)BATCH*CH*LSEQ];   // h1 then h2 (pre-BN),   512MB
__device__ float  g_ctx [(size_t)BATCH*64];        // context vectors, 4MB
__device__ double g_stat[3][2][32];                // [stage][sum|sumsq][channel]

__device__ __forceinline__ float wred32(float v){
#pragma unroll
    for (int o = 16; o > 0; o >>= 1) v += __shfl_xor_sync(0xffffffffu, v, o);
    return v;
}

// ---------------- K0: zero the stat accumulators ---------------------------
__global__ void k_init_stats(){
    int t = threadIdx.x;
    if (t < 192) (&g_stat[0][0][0])[t] = 0.0;
}

// ---------------- K1: conv1 (4->32, k=5, SAME) + bias, stats stage 0 -------
// one block per batch element; 128 threads; each thread -> 2 L positions x 32 ch
__global__ __launch_bounds__(128) void k_conv1(const float* __restrict__ curve,
                                               const float* __restrict__ w,
                                               const float* __restrict__ bias){
    const int b = blockIdx.x;
    const int t = threadIdx.x;
    extern __shared__ float sm[];
    float* xin = sm;              // 4 * 264 (pad 2 each side, stride 264)
    float* ws  = xin + 4*264;     // [i][c][8] padded: 4*32*8 = 1024
    float* cbs = ws  + 1024;      // 32
    float* redS= cbs + 32;        // 32*4
    float* redQ= redS + 128;      // 32*4

    for (int idx = t; idx < 4*264; idx += 128){
        int i = idx / 264, p = idx - i*264, l = p - 2;
        xin[idx] = (l >= 0 && l < LSEQ) ? curve[((size_t)b*4 + i)*LSEQ + l] : 0.f;
    }
    for (int idx = t; idx < 1024; idx += 128){
        int i = idx >> 8, rem = idx & 255, c = rem >> 3, k = rem & 7;
        ws[idx] = (k < 5) ? w[c*20 + i*5 + k] : 0.f;
    }
    if (t < 32) cbs[t] = bias[t];
    __syncthreads();

    const int l0 = 2*t;
    float a0[32], a1[32];
#pragma unroll
    for (int c = 0; c < 32; c++){ a0[c] = cbs[c]; a1[c] = cbs[c]; }

#pragma unroll 1
    for (int i = 0; i < 4; i++){
        const float* xb = xin + i*264 + l0;
        float2 u0 = *(const float2*)(xb);
        float2 u1 = *(const float2*)(xb + 2);
        float2 u2 = *(const float2*)(xb + 4);
        float x0=u0.x, x1=u0.y, x2=u1.x, x3=u1.y, x4=u2.x, x5=u2.y;
        const float* wb = ws + i*256;
#pragma unroll
        for (int c = 0; c < 32; c++){
            float4 wa = *(const float4*)(wb + c*8);
            float  w4 = wb[c*8 + 4];
            a0[c] += wa.x*x0 + wa.y*x1 + wa.z*x2 + wa.w*x3 + w4*x4;
            a1[c] += wa.x*x1 + wa.y*x2 + wa.z*x3 + wa.w*x4 + w4*x5;
        }
    }

    const int wid = t >> 5, lane = t & 31;
    float* outp = g_buf1 + (size_t)b*CH*LSEQ;
#pragma unroll
    for (int c = 0; c < 32; c++){
        *(float2*)(outp + c*LSEQ + l0) = make_float2(a0[c], a1[c]);
        float s = wred32(a0[c] + a1[c]);
        float q = wred32(a0[c]*a0[c] + a1[c]*a1[c]);
        if (lane == 0){ redS[c*4 + wid] = s; redQ[c*4 + wid] = q; }
    }
    __syncthreads();
    if (t < 32){
        double S = 0.0, Q = 0.0;
#pragma unroll
        for (int wI = 0; wI < 4; wI++){ S += redS[t*4+wI]; Q += redQ[t*4+wI]; }
        atomicAdd(&g_stat[0][0][t], S);
        atomicAdd(&g_stat[0][1][t], Q);
    }
}

// ---------------- K2/K3: bn+relu(in) -> conv (32->32, k=3, SAME)+bias ------
// pass 0: g_buf1 -> g_buf2 (stats 0 -> 1);  pass 1: g_buf2 -> g_buf2 (1 -> 2)
__global__ __launch_bounds__(128) void k_rbconv(int pass,
                                                const float* __restrict__ gam,
                                                const float* __restrict__ bet,
                                                const float* __restrict__ w,
                                                const float* __restrict__ cbias){
    const int b = blockIdx.x;
    const int t = threadIdx.x;
    const float* bufIn = (pass == 0) ? g_buf1 : g_buf2;
    float* bufOut = g_buf2;
    const int stIn = pass, stOut = pass + 1;

    extern __shared__ float sm[];
    float* sc  = sm;              // 32
    float* sh  = sc + 32;         // 32
    float* cbs = sh + 32;         // 32
    float* xin = cbs + 32;        // 32*260
    float* ws4 = xin + 32*260;    // [i][c][4]: 4096
    float* redS= ws4 + 4096;      // 128
    float* redQ= redS + 128;      // 128

    if (t < 32){
        const double N = (double)BATCH * (double)LSEQ;
        double S = g_stat[stIn][0][t], Q = g_stat[stIn][1][t];
        double m = S / N, v = Q / N - m*m;
        double s = (double)gam[t] / sqrt(v + EPSBN);
        sc[t] = (float)s;
        sh[t] = (float)((double)bet[t] - m*s);
        cbs[t] = cbias[t];
    }
    __syncthreads();

    const float* inp = bufIn + (size_t)b*CH*LSEQ;
    for (int idx = t; idx < 32*260; idx += 128){
        int i = idx / 260, p = idx - i*260, l = p - 1;
        float val = 0.f;
        if (l >= 0 && l < LSEQ){
            float y = inp[i*LSEQ + l];
            val = fmaxf(sc[i]*y + sh[i], 0.f);
        }
        xin[idx] = val;
    }
    for (int idx = t; idx < 4096; idx += 128){
        int i = idx >> 7, rem = idx & 127, c = rem >> 2, k = rem & 3;
        ws4[idx] = (k < 3) ? w[c*96 + i*3 + k] : 0.f;
    }
    __syncthreads();

    const int l0 = 2*t;
    float a0[32], a1[32];
#pragma unroll
    for (int c = 0; c < 32; c++){ a0[c] = cbs[c]; a1[c] = cbs[c]; }

#pragma unroll 1
    for (int i = 0; i < 32; i++){
        const float* xb = xin + i*260 + l0;
        float2 u0 = *(const float2*)xb;
        float2 u1 = *(const float2*)(xb + 2);
        float x0 = u0.x, x1 = u0.y, x2 = u1.x, x3 = u1.y;
        const float* wb = ws4 + i*128;
#pragma unroll
        for (int c = 0; c < 32; c++){
            float4 wa = *(const float4*)(wb + c*4);
            a0[c] += wa.x*x0 + wa.y*x1 + wa.z*x2;
            a1[c] += wa.x*x1 + wa.y*x2 + wa.z*x3;
        }
    }

    const int wid = t >> 5, lane = t & 31;
    float* outp = bufOut + (size_t)b*CH*LSEQ;
#pragma unroll
    for (int c = 0; c < 32; c++){
        *(float2*)(outp + c*LSEQ + l0) = make_float2(a0[c], a1[c]);
        float s = wred32(a0[c] + a1[c]);
        float q = wred32(a0[c]*a0[c] + a1[c]*a1[c]);
        if (lane == 0){ redS[c*4 + wid] = s; redQ[c*4 + wid] = q; }
    }
    __syncthreads();
    if (t < 32){
        double S = 0.0, Q = 0.0;
#pragma unroll
        for (int wI = 0; wI < 4; wI++){ S += redS[t*4+wI]; Q += redQ[t*4+wI]; }
        atomicAdd(&g_stat[stOut][0][t], S);
        atomicAdd(&g_stat[stOut][1][t], Q);
    }
}

// ---------------- K4: bn0+relu, bn2, residual+relu, mean-pool, linear+tanh -
__global__ __launch_bounds__(256) void k_pool_ctx(const float* __restrict__ gamma1,
                                                  const float* __restrict__ beta1,
                                                  const float* __restrict__ gamma3,
                                                  const float* __restrict__ beta3,
                                                  const float* __restrict__ lin_w,
                                                  const float* __restrict__ lin_b){
    const int b = blockIdx.x;
    const int t = threadIdx.x;
    __shared__ float sc0[32], sh0[32], sc2[32], sh2[32];
    __shared__ float red[32][8];
    __shared__ float pooled[32];

    if (t < 32){
        const double N = (double)BATCH * (double)LSEQ;
        { double S = g_stat[0][0][t], Q = g_stat[0][1][t];
          double m = S/N, v = Q/N - m*m;
          double s = (double)gamma1[t] / sqrt(v + EPSBN);
          sc0[t] = (float)s; sh0[t] = (float)((double)beta1[t] - m*s); }
        { double S = g_stat[2][0][t], Q = g_stat[2][1][t];
          double m = S/N, v = Q/N - m*m;
          double s = (double)gamma3[t] / sqrt(v + EPSBN);
          sc2[t] = (float)s; sh2[t] = (float)((double)beta3[t] - m*s); }
    }
    __syncthreads();

    const float* p1 = g_buf1 + (size_t)b*CH*LSEQ;
    const float* p2 = g_buf2 + (size_t)b*CH*LSEQ;
    const int wid = t >> 5, lane = t & 31;
#pragma unroll 1
    for (int c = 0; c < 32; c++){
        float y1 = p1[c*LSEQ + t];
        float h2 = p2[c*LSEQ + t];
        float x1 = fmaxf(sc0[c]*y1 + sh0[c], 0.f);
        float x2 = fmaxf(sc2[c]*h2 + sh2[c] + x1, 0.f);
        float s = wred32(x2);
        if (lane == 0) red[c][wid] = s;
    }
    __syncthreads();
    if (t < 32){
        float s = 0.f;
#pragma unroll
        for (int wI = 0; wI < 8; wI++) s += red[t][wI];
        pooled[t] = s * (1.f/(float)LSEQ);
    }
    __syncthreads();
    if (t < 64){
        float acc = lin_b[t];
#pragma unroll
        for (int c = 0; c < 32; c++) acc += pooled[c]*lin_w[c*64 + t];
        g_ctx[(size_t)b*64 + t] = tanhf(acc);
    }
}

// ---------------- K5: 10 coupling layers, 64 rows per block, all in smem ---
__global__ __launch_bounds__(256) void k_coupling(const float* __restrict__ zin,
                                                  const float* __restrict__ W1,
                                                  const float* __restrict__ B1,
                                                  const float* __restrict__ W2,
                                                  const float* __restrict__ B2,
                                                  const float* __restrict__ W3,
                                                  const float* __restrict__ B3,
                                                  float* __restrict__ outp){
    const int t = threadIdx.x;
    const int rowBase = blockIdx.x * 64;
    extern __shared__ float sm[];
    float* nin = sm;                 // 64*76  (cols 0..8 = z*mask, 9..72 = ctx)
    float* hA  = nin + 64*76;        // 64*132 (stride 132 avoids bank conflicts)
    float* hB  = hA  + 64*132;       // 64*132
    float* zz  = hB  + 64*132;       // 64*12
    float* ob  = zz  + 64*12;        // 64*20
    float* ldv = ob  + 64*20;        // 64

    for (int idx = t; idx < 64*9; idx += 256){
        int r = idx/9, j = idx - r*9;
        zz[r*12 + j] = zin[(size_t)(rowBase + r)*9 + j];
    }
    for (int idx = t; idx < 64*64; idx += 256){
        int r = idx >> 6, j = idx & 63;
        nin[r*76 + 9 + j] = g_ctx[(size_t)(rowBase + r)*64 + j];
    }
    if (t < 64) ldv[t] = 0.f;
    __syncthreads();

    const int jc = t & 31;           // 4 output columns: 4*jc .. 4*jc+3
    const int r0 = (t >> 5) * 8;     // 8 rows per warp

    for (int layer = 0; layer < 10; ++layer){
        if (t < 64){
#pragma unroll
            for (int j = 0; j < 9; j++){
                float m = (((j + layer) & 1) == 0) ? 1.f : 0.f;
                nin[t*76 + j] = zz[t*12 + j] * m;
            }
        }
        __syncthreads();

        // GEMM1: hA = relu(nin[64x73] @ W1[73x128] + b1)
        {
            const float* Wl = W1 + (size_t)layer*73*128;
            float4 bb = *(const float4*)(B1 + layer*128 + 4*jc);
            float acc[8][4];
#pragma unroll
            for (int r = 0; r < 8; r++){ acc[r][0]=bb.x; acc[r][1]=bb.y; acc[r][2]=bb.z; acc[r][3]=bb.w; }
#pragma unroll 4
            for (int i = 0; i < 73; i++){
                float4 wv = *(const float4*)(Wl + i*128 + 4*jc);
#pragma unroll
                for (int r = 0; r < 8; r++){
                    float x = nin[(r0 + r)*76 + i];
                    acc[r][0] = fmaf(x, wv.x, acc[r][0]);
                    acc[r][1] = fmaf(x, wv.y, acc[r][1]);
                    acc[r][2] = fmaf(x, wv.z, acc[r][2]);
                    acc[r][3] = fmaf(x, wv.w, acc[r][3]);
                }
            }
#pragma unroll
            for (int r = 0; r < 8; r++){
                *(float4*)(hA + (r0 + r)*132 + 4*jc) =
                    make_float4(fmaxf(acc[r][0],0.f), fmaxf(acc[r][1],0.f),
                                fmaxf(acc[r][2],0.f), fmaxf(acc[r][3],0.f));
            }
        }
        __syncthreads();

        // GEMM2: hB = relu(hA[64x128] @ W2[128x128] + b2)
        {
            const float* Wl = W2 + (size_t)layer*128*128;
            float4 bb = *(const float4*)(B2 + layer*128 + 4*jc);
            float acc[8][4];
#pragma unroll
            for (int r = 0; r < 8; r++){ acc[r][0]=bb.x; acc[r][1]=bb.y; acc[r][2]=bb.z; acc[r][3]=bb.w; }
#pragma unroll 4
            for (int i = 0; i < 128; i++){
                float4 wv = *(const float4*)(Wl + i*128 + 4*jc);
#pragma unroll
                for (int r = 0; r < 8; r++){
                    float x = hA[(r0 + r)*132 + i];
                    acc[r][0] = fmaf(x, wv.x, acc[r][0]);
                    acc[r][1] = fmaf(x, wv.y, acc[r][1]);
                    acc[r][2] = fmaf(x, wv.z, acc[r][2]);
                    acc[r][3] = fmaf(x, wv.w, acc[r][3]);
                }
            }
#pragma unroll
            for (int r = 0; r < 8; r++){
                *(float4*)(hB + (r0 + r)*132 + 4*jc) =
                    make_float4(fmaxf(acc[r][0],0.f), fmaxf(acc[r][1],0.f),
                                fmaxf(acc[r][2],0.f), fmaxf(acc[r][3],0.f));
            }
        }
        __syncthreads();

        // GEMM3: ob = hB[64x128] @ W3[128x18] + b3
        {
            const float* Wl = W3 + (size_t)layer*128*18;
            const int r = t >> 2, q = t & 3;
            float acc[5] = {0.f,0.f,0.f,0.f,0.f};
#pragma unroll 2
            for (int i = 0; i < 128; i++){
                float x = hB[r*132 + i];
#pragma unroll
                for (int k = 0; k < 5; k++){
                    int j = q + 4*k;
                    if (j < 18) acc[k] = fmaf(x, __ldg(Wl + i*18 + j), acc[k]);
                }
            }
#pragma unroll
            for (int k = 0; k < 5; k++){
                int j = q + 4*k;
                if (j < 18) ob[r*20 + j] = acc[k] + B3[layer*18 + j];
            }
        }
        __syncthreads();

        // per-row flow update
        if (t < 64){
            float ldl = ldv[t];
#pragma unroll
            for (int j = 0; j < 9; j++){
                if (((j + layer) & 1) != 0){     // unmasked dims
                    float s  = tanhf(ob[t*20 + j]);
                    float tt = ob[t*20 + 9 + j];
                    zz[t*12 + j] = zz[t*12 + j]*expf(s) + tt;
                    ldl += s;
                }
            }
            ldv[t] = ldl;
        }
        __syncthreads();
    }

    if (t < 64){
        float lp = 0.f;
#pragma unroll
        for (int j = 0; j < 9; j++){
            float z = zz[t*12 + j];
            lp += LOG2PI + z*z;
        }
        outp[rowBase + t] = ldv[t] - 0.5f*lp;
    }
}

// ---------------- launch ----------------------------------------------------
extern "C" void kernel_launch(void* const* d_in, const int* in_sizes, int n_in,
                              void* d_out, int out_size){
    const float* inputs  = (const float*)d_in[0];
    const float* curve   = (const float*)d_in[1];
    const float* conv1_w = (const float*)d_in[2];
    const float* conv1_b = (const float*)d_in[3];
    const float* bn1_g   = (const float*)d_in[4];
    const float* bn1_b   = (const float*)d_in[5];
    const float* rb_w1   = (const float*)d_in[6];
    const float* rb_b1   = (const float*)d_in[7];
    const float* rb_g1   = (const float*)d_in[8];
    const float* rb_be1  = (const float*)d_in[9];
    const float* rb_w2   = (const float*)d_in[10];
    const float* rb_b2   = (const float*)d_in[11];
    const float* rb_g2   = (const float*)d_in[12];
    const float* rb_be2  = (const float*)d_in[13];
    const float* lin_w   = (const float*)d_in[14];
    const float* lin_b   = (const float*)d_in[15];
    const float* W1      = (const float*)d_in[16];
    const float* B1      = (const float*)d_in[17];
    const float* W2      = (const float*)d_in[18];
    const float* B2      = (const float*)d_in[19];
    const float* W3      = (const float*)d_in[20];
    const float* B3      = (const float*)d_in[21];
    float* out = (float*)d_out;

    const int smem1 = (4*264 + 1024 + 32 + 128 + 128) * 4;
    const int smemR = (32 + 32 + 32 + 32*260 + 4096 + 128 + 128) * 4;
    const int smemC = (64*76 + 64*132*2 + 64*12 + 64*20 + 64) * 4;

    cudaFuncSetAttribute(k_conv1,    cudaFuncAttributeMaxDynamicSharedMemorySize, smem1);
    cudaFuncSetAttribute(k_rbconv,   cudaFuncAttributeMaxDynamicSharedMemorySize, smemR);
    cudaFuncSetAttribute(k_coupling, cudaFuncAttributeMaxDynamicSharedMemorySize, smemC);

    k_init_stats<<<1, 192>>>();
    k_conv1<<<BATCH, 128, smem1>>>(curve, conv1_w, conv1_b);
    k_rbconv<<<BATCH, 128, smemR>>>(0, bn1_g, bn1_b, rb_w1, rb_b1);
    k_rbconv<<<BATCH, 128, smemR>>>(1, rb_g1, rb_be1, rb_w2, rb_b2);
    k_pool_ctx<<<BATCH, 256>>>(bn1_g, bn1_b, rb_g2, rb_be2, lin_w, lin_b);
    k_coupling<<<BATCH/64, 256, smemC>>>(inputs, W1, B1, W2, B2, W3, B3, out);
}